// round 14
// baseline (speedup 1.0000x reference)
#include <cuda_runtime.h>
#include <cuda_fp16.h>

// ---------------- problem constants ----------------
#define V_N   7
#define NB    256
#define KTOT  16384      // C*T
#define OE    256
#define MTOT  1792       // NB * V_N
#define H_NSTR 114688    // C*T*V
#define H_CSTR 448       // T*V

// ---------------- GEMM tiling ----------------
#define MT    128        // M rows per CTA (14 M-blocks)
#define NROWS 20         // max batch rows touched per M-block
#define KTILE 64
#define NKT_TOTAL 256    // KTOT / KTILE
#define MAXSPLIT 11

// SMEM stage layout
#define AS_NSTR 452                   // floats per n row (448 data + 4 pad)
#define AS_BYTES (NROWS * AS_NSTR * 4)  // 36160
#define B_BYTES  (KTILE * OE * 2)       // 32768 (fp16)
#define STAGE_B  (AS_BYTES + B_BYTES)   // 68928
#define NSTAGE   3
#define SMEM_BYTES (NSTAGE * STAGE_B)   // 206784

// ---------------- device scratch ----------------
__device__ __half g_Wh[KTOT * OE];               // fp16 fragment/swizzled W^T (8.4 MB)
__device__ float  g_part[MAXSPLIT * MTOT * OE];  // K-split partial Wh (20.2 MB)
__device__ float  g_adjn[49];

// ---------------- helpers ----------------
__device__ __forceinline__ unsigned smem_u32(const void* p) {
    unsigned a;
    asm("{ .reg .u64 t; cvta.to.shared.u64 t, %1; cvt.u32.u64 %0, t; }" : "=r"(a) : "l"(p));
    return a;
}
__device__ __forceinline__ unsigned pk2h(float lo, float hi) {
    unsigned r;
    asm("cvt.rn.f16x2.f32 %0, %1, %2;" : "=r"(r) : "f"(hi), "f"(lo));
    return r;
}
#define CP_ASYNC_16(dst_u32, src) \
    asm volatile("cp.async.cg.shared.global [%0], [%1], 16;" :: "r"(dst_u32), "l"(src) : "memory")
#define CP_COMMIT() asm volatile("cp.async.commit_group;" ::: "memory")
#define CP_WAIT1()  asm volatile("cp.async.wait_group 1;" ::: "memory")

#define MMA_F16(c, A, B0, B1) \
    asm volatile("mma.sync.aligned.m16n8k16.row.col.f32.f16.f16.f32 " \
                 "{%0,%1,%2,%3},{%4,%5,%6,%7},{%8,%9},{%0,%1,%2,%3};\n" \
                 : "+f"(c[0]), "+f"(c[1]), "+f"(c[2]), "+f"(c[3]) \
                 : "r"(A[0]), "r"(A[1]), "r"(A[2]), "r"(A[3]), "r"(B0), "r"(B1))

// ================= prep: W (f32) -> g_Wh (fp16, per-k32 swizzled frag layout), streaming ===
__global__ void __launch_bounds__(256) prep_kernel(const float* __restrict__ W,
                                                   const float* __restrict__ Bp) {
    const int gid = blockIdx.x * 256 + threadIdx.x;   // 2048 blocks -> 524288 granules
    const int tile = gid >> 10, rem = gid & 1023;
    const int c = rem >> 2, t4 = rem & 3;
    const float* wp = W + (size_t)(tile * 32 + 2 * t4) * OE + c;
    float v0 = wp[0 * OE],  v1 = wp[1 * OE];
    float v2 = wp[8 * OE],  v3 = wp[9 * OE];
    float v4 = wp[16 * OE], v5 = wp[17 * OE];
    float v6 = wp[24 * OE], v7 = wp[25 * OE];
    unsigned p00 = pk2h(v0, v1), p01 = pk2h(v2, v3);
    unsigned p10 = pk2h(v4, v5), p11 = pk2h(v6, v7);
    uint4 o = ((c >> 1) & 1) ? make_uint4(p10, p11, p00, p01)
                             : make_uint4(p00, p01, p10, p11);
    ((uint4*)g_Wh)[gid] = o;

    if (blockIdx.x == 0 && threadIdx.x == 0) {
        float adj[49];
        float mn = 1e30f, mx = -1e30f;
        for (int k = 0; k < 49; k++) {
            float x = Bp[k] + 1e-6f + ((k / 7) == (k % 7) ? 1.0f : 0.0f);
            adj[k] = x;
            mn = fminf(mn, x);
            mx = fmaxf(mx, x);
        }
        float inv = 1.0f / (mx - mn);
        float dsum[7];
        for (int i2 = 0; i2 < 7; i2++) {
            float sum = 0.0f;
            for (int j = 0; j < 7; j++) {
                adj[i2 * 7 + j] = (adj[i2 * 7 + j] - mn) * inv;
                sum += adj[i2 * 7 + j];
            }
            dsum[i2] = sum;
        }
        for (int i2 = 0; i2 < 7; i2++) {
            float di = 1.0f / sqrtf(dsum[i2]);
            for (int j = 0; j < 7; j++)
                g_adjn[i2 * 7 + j] = adj[i2 * 7 + j] * di / sqrtf(dsum[j]);
        }
    }
}

// ================= main GEMM: partial Wh = hf @ W (fp16 mma.sync, f32 accum) =============
// grid = 148 CTAs: 14 M-blocks (MT=128); first 8 get 11 K-splits, last 6 get 10.
__global__ void __launch_bounds__(512, 1) gemm_kernel(const float* __restrict__ h) {
    extern __shared__ float sm[];
    const unsigned smem_base = smem_u32(sm);
    const int tid = threadIdx.x;
    const int bid = blockIdx.x;

    int mb, sp, s_cnt;
    if (bid < 88) { mb = bid / 11; sp = bid - mb * 11; s_cnt = 11; }
    else { int r = bid - 88; int q = r / 10; mb = 8 + q; sp = r - q * 10; s_cnt = 10; }
    const int base_t = NKT_TOTAL / s_cnt, rem = NKT_TOTAL % s_cnt;
    const int cnt   = base_t + (sp < rem ? 1 : 0);
    const int start = sp * base_t + (sp < rem ? sp : rem);
    const int m0 = mb * MT;
    const int n_first = m0 / 7;
    const int n_last  = (m0 + MT - 1) / 7;
    const int nCnt = n_last - n_first + 1;      // 19 or 20
    const int nA = nCnt * 112;                  // A float4 slots

    // ---- staging slots: <=2240 A float4 + 2048 B 16B-chunks (B region at 2240) ----
    int srcOff[9]; unsigned dstOff[9];
    bool isB[9], valid[9];
#pragma unroll
    for (int q = 0; q < 9; q++) {
        int f = tid + q * 512;
        if (f < 2240) {
            int nr = f / 112, s4 = f - nr * 112;
            isB[q] = false;
            valid[q] = (f < nA);
            srcOff[q] = (n_first + nr) * H_NSTR + s4 * 4;
            dstOff[q] = (unsigned)(nr * (AS_NSTR * 4) + s4 * 16);
        } else {
            int b = f - 2240;
            isB[q] = true;
            valid[q] = (b < 2048);
            srcOff[q] = b * 8;                  // half offset in k64 chunk
            dstOff[q] = (unsigned)(AS_BYTES + b * 16);
        }
    }

    // ---- fragment geometry (general m/7 gather; 32 units, 2 per warp) ----
    const int w = tid >> 5, lane = tid & 31;
    const int g = lane >> 2, t4 = lane & 3;
    const int un = w & 3;
    int um[2]; int baseA[2][2];
#pragma unroll
    for (int ui = 0; ui < 2; ui++) {
        int u = (ui == 0) ? w : (w + 16);
        um[ui] = u >> 2;
#pragma unroll
        for (int r = 0; r < 2; r++) {
            int gm = m0 + um[ui] * 16 + g + r * 8;
            int gn = gm / 7;
            baseA[ui][r] = (gn - n_first) * AS_NSTR + (gm - gn * 7);
        }
    }
    const int xg = (g >> 1) & 1;
    const unsigned bThread = (unsigned)((un * 64 + g) * 64);

    float acc[2][8][4];
#pragma unroll
    for (int ui = 0; ui < 2; ui++)
#pragma unroll
        for (int nt = 0; nt < 8; nt++)
#pragma unroll
            for (int r = 0; r < 4; r++) acc[ui][nt][r] = 0.0f;

    auto issue = [&](int it, int buf) {
        const int kt = start + it;
        const unsigned sb = smem_base + (unsigned)(buf * STAGE_B);
        const float* ha = h + kt * H_CSTR;
        const __half* wb = g_Wh + (size_t)kt * 16384;
#pragma unroll
        for (int q = 0; q < 9; q++) {
            if (!valid[q]) continue;
            if (isB[q]) CP_ASYNC_16(sb + dstOff[q], wb + srcOff[q]);
            else        CP_ASYNC_16(sb + dstOff[q], ha + srcOff[q]);
        }
    };

    issue(0, 0); CP_COMMIT();
    issue(1, 1); CP_COMMIT();

    int buf = 0, buf2 = 2;
    for (int it = 0; it < cnt; ++it) {
        CP_WAIT1();
        __syncthreads();
        if (it + 2 < cnt) issue(it + 2, buf2);
        CP_COMMIT();

        const float* As = sm + buf * (STAGE_B / 4);
        const char*  Bs = (const char*)sm + buf * STAGE_B + AS_BYTES;

#pragma unroll
        for (int kg = 0; kg < 4; kg++) {
            const int ko = (kg * 16 + 2 * t4) * 7;
            unsigned afr[2][4];
            afr[0][0] = pk2h(As[baseA[0][0] + ko],      As[baseA[0][0] + ko + 7]);
            afr[0][1] = pk2h(As[baseA[0][1] + ko],      As[baseA[0][1] + ko + 7]);
            afr[0][2] = pk2h(As[baseA[0][0] + ko + 56], As[baseA[0][0] + ko + 63]);
            afr[0][3] = pk2h(As[baseA[0][1] + ko + 56], As[baseA[0][1] + ko + 63]);
            afr[1][0] = pk2h(As[baseA[1][0] + ko],      As[baseA[1][0] + ko + 7]);
            afr[1][1] = pk2h(As[baseA[1][1] + ko],      As[baseA[1][1] + ko + 7]);
            afr[1][2] = pk2h(As[baseA[1][0] + ko + 56], As[baseA[1][0] + ko + 63]);
            afr[1][3] = pk2h(As[baseA[1][1] + ko + 56], As[baseA[1][1] + ko + 63]);
            const char* bbase = Bs + (kg >> 1) * 16384 +
                                (unsigned)((((2 * t4 + (kg & 1)) ^ xg)) * 8) + bThread;
#pragma unroll
            for (int nt = 0; nt < 8; nt++) {
                uint2 b = *(const uint2*)(bbase + nt * 512);
                MMA_F16(acc[0][nt], afr[0], b.x, b.y);
                MMA_F16(acc[1][nt], afr[1], b.x, b.y);
            }
        }
        buf = (buf == 2) ? 0 : buf + 1;
        buf2 = (buf2 == 2) ? 0 : buf2 + 1;
    }

    // ---- epilogue ----
    float* op = g_part + ((size_t)sp * MTOT + m0) * OE;
#pragma unroll
    for (int ui = 0; ui < 2; ui++) {
#pragma unroll
        for (int nt = 0; nt < 8; nt++) {
            int r = um[ui] * 16 + g;
            int c = un * 64 + nt * 8 + 2 * t4;
            *(float2*)&op[(size_t)r * OE + c]       = make_float2(acc[ui][nt][0], acc[ui][nt][1]);
            *(float2*)&op[(size_t)(r + 8) * OE + c] = make_float2(acc[ui][nt][2], acc[ui][nt][3]);
        }
    }
}

// ================= tail: one n per block, 512 threads; per-v split count ==============
__global__ void __launch_bounds__(512) tail_kernel(const float* __restrict__ a,
                                                   float* __restrict__ out) {
    __shared__ float whh[7][260];          // half-1 partial wh contributions
    __shared__ float red1[8][7], red2[8][7];
    __shared__ float s1s[7], s2s[7];
    __shared__ float adjn_s[49], att[49], att2[49];

    const int tid  = threadIdx.x;
    const int half = tid >> 8;             // 0/1
    const int o    = tid & 255;
    const int n    = blockIdx.x;           // grid = 256

    // per-v split count: M-block of row m = n*7+v is m>>7; first 8 blocks have 11 splits
    float wh[7];
#pragma unroll
    for (int v = 0; v < 7; v++) {
        wh[v] = 0.0f;
        const int m = n * 7 + v;
        const int sc = ((m >> 7) < 8) ? 11 : 10;
        const int lo = half ? 6 : 0;
        const int hi = half ? sc : 6;
        const float* p = &g_part[(size_t)m * OE + o];
        for (int ksi = lo; ksi < hi; ksi++)
            wh[v] += __ldg(p + (size_t)ksi * MTOT * OE);
    }
    if (half == 1) {
#pragma unroll
        for (int v = 0; v < 7; v++) whh[v][o] = wh[v];
    }
    if (tid < 49) adjn_s[tid] = g_adjn[tid];
    __syncthreads();

    const float a1 = __ldg(&a[o]);
    const float a2 = __ldg(&a[OE + o]);
    const int wid = o >> 5, lane = o & 31;

    if (half == 0) {
#pragma unroll
        for (int v = 0; v < 7; v++) wh[v] += whh[v][o];
#pragma unroll
        for (int v = 0; v < 7; v++) {
            float p1 = wh[v] * a1;
            float p2 = wh[v] * a2;
#pragma unroll
            for (int off = 16; off > 0; off >>= 1) {
                p1 += __shfl_down_sync(0xffffffffu, p1, off);
                p2 += __shfl_down_sync(0xffffffffu, p2, off);
            }
            if (lane == 0) { red1[wid][v] = p1; red2[wid][v] = p2; }
        }
    }
    __syncthreads();
    if (tid < 7) {
        float s = 0.0f;
        for (int w2 = 0; w2 < 8; w2++) s += red1[w2][tid];
        s1s[tid] = s;
    } else if (tid >= 32 && tid < 39) {
        float s = 0.0f;
        for (int w2 = 0; w2 < 8; w2++) s += red2[w2][tid - 32];
        s2s[tid - 32] = s;
    }
    __syncthreads();
    if (tid < 7) {
        float e[7];
        float mx = -1e30f;
#pragma unroll
        for (int j = 0; j < 7; j++) {
            float x = s1s[tid] + s2s[j];
            x = (x >= 0.0f) ? x : 0.2f * x;   // leaky_relu alpha=0.2
            e[j] = x;
            mx = fmaxf(mx, x);
        }
        float sum = 0.0f;
#pragma unroll
        for (int j = 0; j < 7; j++) { e[j] = expf(e[j] - mx); sum += e[j]; }
        float inv = 1.0f / sum;
#pragma unroll
        for (int j = 0; j < 7; j++) att[tid * 7 + j] = e[j] * inv;
    }
    __syncthreads();
    if (tid < 49) {
        int i = tid / 7, kcol = tid - i * 7;
        float s = 0.0f;
#pragma unroll
        for (int j = 0; j < 7; j++) s += adjn_s[i * 7 + j] * att[j * 7 + kcol];
        att2[tid] = s;
    }
    __syncthreads();
    if (half == 0) {
#pragma unroll
        for (int v = 0; v < 7; v++) {
            float s = 0.0f;
#pragma unroll
            for (int j = 0; j < 7; j++) s += att2[v * 7 + j] * wh[j];
            out[((size_t)n * 7 + v) * OE + o] = (s > 0.0f) ? s : expm1f(s);  // elu
        }
    }
}

// ================= launch =================
extern "C" void kernel_launch(void* const* d_in, const int* in_sizes, int n_in,
                              void* d_out, int out_size) {
    const float* h  = (const float*)d_in[0];   // (256,256,64,7)
    const float* W  = (const float*)d_in[1];   // (16384,256)
    const float* a  = (const float*)d_in[2];   // (512,1)
    const float* Bp = (const float*)d_in[3];   // (7,7)
    float* out = (float*)d_out;                // (256,7,256)

    prep_kernel<<<2048, 256>>>(W, Bp);

    cudaFuncSetAttribute(gemm_kernel, cudaFuncAttributeMaxDynamicSharedMemorySize, SMEM_BYTES);
    gemm_kernel<<<148, 512, SMEM_BYTES>>>(h);

    tail_kernel<<<NB, 512>>>(a, out);
}

// round 15
// speedup vs baseline: 1.2954x; 1.2954x over previous
#include <cuda_runtime.h>
#include <cuda_fp16.h>

// ---------------- problem constants ----------------
#define V_N   7
#define NB    256
#define KTOT  16384      // C*T
#define OE    256
#define MTOT  1792       // NB * V_N
#define H_NSTR 114688    // C*T*V
#define H_CSTR 448       // T*V

// ---------------- GEMM tiling ----------------
#define MT    112        // M rows per CTA (= 16 batch rows exactly)
#define NPB   16         // batch rows per M-block
#define KTILE 64
#define NKT_TOTAL 256    // KTOT / KTILE
#define MAXSPLIT 10

// SMEM stage layout
#define AS_NSTR 456                   // floats per n row (448 data + 8 pad)
#define AS_BYTES (NPB * AS_NSTR * 4)  // 29184
#define B_BYTES  (KTILE * OE * 2)     // 32768 (fp16)
#define STAGE_B  (AS_BYTES + B_BYTES) // 61952
#define NSTAGE   3
#define SMEM_BYTES (NSTAGE * STAGE_B) // 185856

// ---------------- device scratch ----------------
__device__ __half g_Wh[KTOT * OE];               // fp16 fragment/swizzled W^T (8.4 MB)
__device__ float  g_part[MAXSPLIT * MTOT * OE];  // K-split partial Wh

// ---------------- helpers ----------------
__device__ __forceinline__ unsigned smem_u32(const void* p) {
    unsigned a;
    asm("{ .reg .u64 t; cvta.to.shared.u64 t, %1; cvt.u32.u64 %0, t; }" : "=r"(a) : "l"(p));
    return a;
}
__device__ __forceinline__ unsigned pk2h(float lo, float hi) {
    unsigned r;
    asm("cvt.rn.f16x2.f32 %0, %1, %2;" : "=r"(r) : "f"(hi), "f"(lo));
    return r;
}
#define CP_ASYNC_16(dst_u32, src) \
    asm volatile("cp.async.cg.shared.global [%0], [%1], 16;" :: "r"(dst_u32), "l"(src) : "memory")
#define CP_COMMIT() asm volatile("cp.async.commit_group;" ::: "memory")
#define CP_WAIT1()  asm volatile("cp.async.wait_group 1;" ::: "memory")

#define MMA_F16(c, A, B0, B1) \
    asm volatile("mma.sync.aligned.m16n8k16.row.col.f32.f16.f16.f32 " \
                 "{%0,%1,%2,%3},{%4,%5,%6,%7},{%8,%9},{%0,%1,%2,%3};\n" \
                 : "+f"(c[0]), "+f"(c[1]), "+f"(c[2]), "+f"(c[3]) \
                 : "r"(A[0]), "r"(A[1]), "r"(A[2]), "r"(A[3]), "r"(B0), "r"(B1))

// ================= prep: W (f32) -> g_Wh (fp16, per-k32 swizzled frag layout), streaming ===
// Output granule gid (16B) = (tile, c, t4): fp16 pairs for k = tile*32 + 2*t4 + {0,8,16,24}
// (+1 each); low/high 8B swapped when (c>>1)&1. No adj code here -> low regs -> high occ.
__global__ void __launch_bounds__(256, 4) prep_kernel(const float* __restrict__ W) {
    const int gid = blockIdx.x * 256 + threadIdx.x;   // 2048 blocks -> 524288 granules
    const int tile = gid >> 10, rem = gid & 1023;
    const int c = rem >> 2, t4 = rem & 3;
    const float* wp = W + (size_t)(tile * 32 + 2 * t4) * OE + c;
    float v0 = wp[0 * OE],  v1 = wp[1 * OE];
    float v2 = wp[8 * OE],  v3 = wp[9 * OE];
    float v4 = wp[16 * OE], v5 = wp[17 * OE];
    float v6 = wp[24 * OE], v7 = wp[25 * OE];
    unsigned p00 = pk2h(v0, v1), p01 = pk2h(v2, v3);
    unsigned p10 = pk2h(v4, v5), p11 = pk2h(v6, v7);
    uint4 o = ((c >> 1) & 1) ? make_uint4(p10, p11, p00, p01)
                             : make_uint4(p00, p01, p10, p11);
    ((uint4*)g_Wh)[gid] = o;
}

// ================= main GEMM: partial Wh = hf @ W (fp16 mma.sync, f32 accum) =============
// grid = 148 CTAs: first 4 M-blocks get 10 K-splits, last 12 get 9.
__global__ void __launch_bounds__(512, 1) gemm_kernel(const float* __restrict__ h) {
    extern __shared__ float sm[];
    const unsigned smem_base = smem_u32(sm);
    const int tid = threadIdx.x;
    const int bid = blockIdx.x;

    int mb, sp, s_cnt;
    if (bid < 40) { mb = bid / 10; sp = bid - mb * 10; s_cnt = 10; }
    else { int r = bid - 40; mb = 4 + r / 9; sp = r - (mb - 4) * 9; s_cnt = 9; }
    const int base_t = NKT_TOTAL / s_cnt, rem = NKT_TOTAL % s_cnt;
    const int cnt   = base_t + (sp < rem ? 1 : 0);
    const int start = sp * base_t + (sp < rem ? sp : rem);
    const int m0 = mb * MT;
    const int n_first = mb * NPB;

    // ---- staging slots: 1792 A float4 + 2048 B 16B-chunks = 3840 ----
    int srcOff[8]; unsigned dstOff[8];
    bool isB[8], valid[8];
#pragma unroll
    for (int q = 0; q < 8; q++) {
        int f = tid + q * 512;
        valid[q] = (f < 3840);
        if (f < 1792) {
            int nr = f / 112, s4 = f - nr * 112;
            isB[q] = false;
            srcOff[q] = (n_first + nr) * H_NSTR + s4 * 4;
            dstOff[q] = (unsigned)(nr * AS_NSTR * 4 + s4 * 16);
        } else {
            int b = f - 1792;
            isB[q] = true;
            srcOff[q] = b * 8;
            dstOff[q] = (unsigned)(AS_BYTES + b * 16);
        }
    }

    // ---- fragment geometry ----
    const int w = tid >> 5, lane = tid & 31;
    const int g = lane >> 2, t4 = lane & 3;
    const int nu = (w < 12) ? 2 : 1;
    const int un = w & 3;
    int um[2]; int baseA[2][2];
#pragma unroll
    for (int ui = 0; ui < 2; ui++) {
        int u = (ui == 0) ? w : (w + 16);
        um[ui] = u >> 2;
#pragma unroll
        for (int r = 0; r < 2; r++) {
            int m = um[ui] * 16 + g + r * 8;
            int nr = m / 7;
            baseA[ui][r] = nr * AS_NSTR + (m - nr * 7);
        }
    }
    const int xg = (g >> 1) & 1;
    const unsigned bThread = (unsigned)((un * 64 + g) * 64);

    float acc[2][8][4];
#pragma unroll
    for (int ui = 0; ui < 2; ui++)
#pragma unroll
        for (int nt = 0; nt < 8; nt++)
#pragma unroll
            for (int r = 0; r < 4; r++) acc[ui][nt][r] = 0.0f;

    auto issue = [&](int it, int buf) {
        const int kt = start + it;
        const unsigned sb = smem_base + (unsigned)(buf * STAGE_B);
        const float* ha = h + kt * H_CSTR;
        const __half* wb = g_Wh + (size_t)kt * 16384;
#pragma unroll
        for (int q = 0; q < 8; q++) {
            if (!valid[q]) continue;
            if (isB[q]) CP_ASYNC_16(sb + dstOff[q], wb + srcOff[q]);
            else        CP_ASYNC_16(sb + dstOff[q], ha + srcOff[q]);
        }
    };

    issue(0, 0); CP_COMMIT();
    issue(1, 1); CP_COMMIT();

    int buf = 0, buf2 = 2;
    for (int it = 0; it < cnt; ++it) {
        CP_WAIT1();
        __syncthreads();
        if (it + 2 < cnt) issue(it + 2, buf2);
        CP_COMMIT();

        const float* As = sm + buf * (STAGE_B / 4);
        const char*  Bs = (const char*)sm + buf * STAGE_B + AS_BYTES;

#pragma unroll
        for (int kg = 0; kg < 4; kg++) {
            const int ko = (kg * 16 + 2 * t4) * 7;
            unsigned afr[2][4];
            afr[0][0] = pk2h(As[baseA[0][0] + ko],      As[baseA[0][0] + ko + 7]);
            afr[0][1] = pk2h(As[baseA[0][1] + ko],      As[baseA[0][1] + ko + 7]);
            afr[0][2] = pk2h(As[baseA[0][0] + ko + 56], As[baseA[0][0] + ko + 63]);
            afr[0][3] = pk2h(As[baseA[0][1] + ko + 56], As[baseA[0][1] + ko + 63]);
            if (nu == 2) {
                afr[1][0] = pk2h(As[baseA[1][0] + ko],      As[baseA[1][0] + ko + 7]);
                afr[1][1] = pk2h(As[baseA[1][1] + ko],      As[baseA[1][1] + ko + 7]);
                afr[1][2] = pk2h(As[baseA[1][0] + ko + 56], As[baseA[1][0] + ko + 63]);
                afr[1][3] = pk2h(As[baseA[1][1] + ko + 56], As[baseA[1][1] + ko + 63]);
            }
            const char* bbase = Bs + (kg >> 1) * 16384 +
                                (unsigned)((((2 * t4 + (kg & 1)) ^ xg)) * 8) + bThread;
#pragma unroll
            for (int nt = 0; nt < 8; nt++) {
                uint2 b = *(const uint2*)(bbase + nt * 512);
                MMA_F16(acc[0][nt], afr[0], b.x, b.y);
                if (nu == 2) MMA_F16(acc[1][nt], afr[1], b.x, b.y);
            }
        }
        buf = (buf == 2) ? 0 : buf + 1;
        buf2 = (buf2 == 2) ? 0 : buf2 + 1;
    }

    // ---- epilogue ----
    float* op = g_part + ((size_t)sp * MTOT + m0) * OE;
#pragma unroll
    for (int ui = 0; ui < 2; ui++) {
        if (ui >= nu) break;
#pragma unroll
        for (int nt = 0; nt < 8; nt++) {
            int r = um[ui] * 16 + g;
            int c = un * 64 + nt * 8 + 2 * t4;
            *(float2*)&op[(size_t)r * OE + c]       = make_float2(acc[ui][nt][0], acc[ui][nt][1]);
            *(float2*)&op[(size_t)(r + 8) * OE + c] = make_float2(acc[ui][nt][2], acc[ui][nt][3]);
        }
    }
}

// ================= tail: one n per block, 512 threads; adj computed in-block ============
__global__ void __launch_bounds__(512) tail_kernel(const float* __restrict__ a,
                                                   const float* __restrict__ Bp,
                                                   float* __restrict__ out) {
    __shared__ float whh[7][260];          // half-1 partial wh contributions
    __shared__ float red1[8][7], red2[8][7];
    __shared__ float s1s[7], s2s[7];
    __shared__ float adjv[49], adjn_s[49], att[49], att2[49];

    const int tid  = threadIdx.x;
    const int half = tid >> 8;             // 0/1
    const int o    = tid & 255;
    const int n    = blockIdx.x;           // grid = 256
    const int s_cnt = ((n >> 4) < 4) ? 10 : 9;
    const int kmid  = s_cnt >> 1;
    const int kA = half ? kmid : 0;
    const int kB = half ? s_cnt : kmid;

    // stage raw adjacency (before any use; one barrier)
    if (tid < 49)
        adjv[tid] = Bp[tid] + 1e-6f + ((tid / 7) == (tid % 7) ? 1.0f : 0.0f);
    __syncthreads();

    // each half accumulates its K-split range: 7 independent load chains per thread
    float wh[7];
#pragma unroll
    for (int v = 0; v < 7; v++) wh[v] = 0.0f;
    for (int ksi = kA; ksi < kB; ksi++) {
        const float* p = &g_part[((size_t)ksi * MTOT + n * 7) * OE + o];
#pragma unroll
        for (int v = 0; v < 7; v++) wh[v] += __ldg(p + v * OE);
    }
    if (half == 1) {
#pragma unroll
        for (int v = 0; v < 7; v++) whh[v][o] = wh[v];
    }

    // thread 256 (lane 0 of the first half-1 warp) normalizes adj while others load
    if (tid == 256) {
        float mn = 1e30f, mx = -1e30f;
#pragma unroll 7
        for (int k = 0; k < 49; k++) {
            mn = fminf(mn, adjv[k]);
            mx = fmaxf(mx, adjv[k]);
        }
        float inv = 1.0f / (mx - mn);
        float dsum[7];
#pragma unroll
        for (int i2 = 0; i2 < 7; i2++) {
            float s = 0.0f;
#pragma unroll
            for (int j = 0; j < 7; j++) s += (adjv[i2 * 7 + j] - mn) * inv;
            dsum[i2] = rsqrtf(s);
        }
#pragma unroll
        for (int i2 = 0; i2 < 7; i2++)
#pragma unroll
            for (int j = 0; j < 7; j++)
                adjn_s[i2 * 7 + j] = (adjv[i2 * 7 + j] - mn) * inv * dsum[i2] * dsum[j];
    }
    __syncthreads();

    const float a1 = __ldg(&a[o]);
    const float a2 = __ldg(&a[OE + o]);
    const int wid = o >> 5, lane = o & 31;

    if (half == 0) {
#pragma unroll
        for (int v = 0; v < 7; v++) wh[v] += whh[v][o];
#pragma unroll
        for (int v = 0; v < 7; v++) {
            float p1 = wh[v] * a1;
            float p2 = wh[v] * a2;
#pragma unroll
            for (int off = 16; off > 0; off >>= 1) {
                p1 += __shfl_down_sync(0xffffffffu, p1, off);
                p2 += __shfl_down_sync(0xffffffffu, p2, off);
            }
            if (lane == 0) { red1[wid][v] = p1; red2[wid][v] = p2; }
        }
    }
    __syncthreads();
    if (tid < 7) {
        float s = 0.0f;
        for (int w2 = 0; w2 < 8; w2++) s += red1[w2][tid];
        s1s[tid] = s;
    } else if (tid >= 32 && tid < 39) {
        float s = 0.0f;
        for (int w2 = 0; w2 < 8; w2++) s += red2[w2][tid - 32];
        s2s[tid - 32] = s;
    }
    __syncthreads();
    if (tid < 7) {
        float e[7];
        float mx = -1e30f;
#pragma unroll
        for (int j = 0; j < 7; j++) {
            float x = s1s[tid] + s2s[j];
            x = (x >= 0.0f) ? x : 0.2f * x;   // leaky_relu alpha=0.2
            e[j] = x;
            mx = fmaxf(mx, x);
        }
        float sum = 0.0f;
#pragma unroll
        for (int j = 0; j < 7; j++) { e[j] = expf(e[j] - mx); sum += e[j]; }
        float inv = 1.0f / sum;
#pragma unroll
        for (int j = 0; j < 7; j++) att[tid * 7 + j] = e[j] * inv;
    }
    __syncthreads();
    if (tid < 49) {
        int i = tid / 7, kcol = tid - i * 7;
        float s = 0.0f;
#pragma unroll
        for (int j = 0; j < 7; j++) s += adjn_s[i * 7 + j] * att[j * 7 + kcol];
        att2[tid] = s;
    }
    __syncthreads();
    if (half == 0) {
#pragma unroll
        for (int v = 0; v < 7; v++) {
            float s = 0.0f;
#pragma unroll
            for (int j = 0; j < 7; j++) s += att2[v * 7 + j] * wh[j];
            out[((size_t)n * 7 + v) * OE + o] = (s > 0.0f) ? s : expm1f(s);  // elu
        }
    }
}

// ================= launch =================
extern "C" void kernel_launch(void* const* d_in, const int* in_sizes, int n_in,
                              void* d_out, int out_size) {
    const float* h  = (const float*)d_in[0];   // (256,256,64,7)
    const float* W  = (const float*)d_in[1];   // (16384,256)
    const float* a  = (const float*)d_in[2];   // (512,1)
    const float* Bp = (const float*)d_in[3];   // (7,7)
    float* out = (float*)d_out;                // (256,7,256)

    prep_kernel<<<2048, 256>>>(W);

    cudaFuncSetAttribute(gemm_kernel, cudaFuncAttributeMaxDynamicSharedMemorySize, SMEM_BYTES);
    gemm_kernel<<<148, 512, SMEM_BYTES>>>(h);

    tail_kernel<<<NB, 512>>>(a, Bp, out);
}